// round 14
// baseline (speedup 1.0000x reference)
#include <cuda_runtime.h>

#define NP 65536          // cells per batch (256*256)
#define NCOLS 256
#define NBATCH 32
#define CTA 128

typedef unsigned long long u64;

// Wx + biases + Wo in constant memory (uniform port); Wh in SMEM (L1 port).
__constant__ __align__(16) float cWx[9 * 64];
__constant__ __align__(16) float cB[64];
__constant__ __align__(16) float cWo[16 * 9];
__constant__ __align__(16) float cBo[9];

__device__ __forceinline__ float tanh_f(float x) {
    float y; asm("tanh.approx.f32 %0, %1;" : "=f"(y) : "f"(x)); return y;
}
__device__ __forceinline__ float sig_f(float x) {
    return fmaf(0.5f, tanh_f(0.5f * x), 0.5f);
}
__device__ __forceinline__ u64 pack2(float a, float b) {
    u64 v; asm("mov.b64 %0, {%1, %2};" : "=l"(v) : "f"(a), "f"(b)); return v;
}
__device__ __forceinline__ void unpack2(u64 v, float& a, float& b) {
    asm("mov.b64 {%0, %1}, %2;" : "=f"(a), "=f"(b) : "l"(v));
}
// packed f32x2 FMA: acc.lo += m.lo*w.lo ; acc.hi += m.hi*w.hi
#define FMA2(acc, m, w) asm("fma.rn.f32x2 %0, %1, %2, %0;" : "+l"(acc) : "l"(m), "l"(w))

// One 16-gate block (blk in {0:i,1:f,2:g,3:o}) for two cells, gate-pair packed.
// Wx pairs from constant port; Wh pairs from SMEM; h pairs (pre-duplicated
// f32x2) stream from per-thread SMEM columns (LDS.64, conflict-free).
__device__ __forceinline__ void gate_block2(
    const float* sWh, const u64* sH0, const u64* sH1, int tid, int blk,
    const float* x0, const float* x1,
    u64* a0, u64* a1)
{
    const u64* bp = (const u64*)(cB + blk * 16);
    #pragma unroll
    for (int j = 0; j < 8; j++) { u64 bv = bp[j]; a0[j] = bv; a1[j] = bv; }

    #pragma unroll
    for (int k = 0; k < 9; k++) {
        const u64* wr = (const u64*)(cWx + k * 64 + blk * 16);
        u64 xa = pack2(x0[k], x0[k]);
        u64 xb = pack2(x1[k], x1[k]);
        #pragma unroll
        for (int q = 0; q < 8; q++) {
            u64 w = wr[q];
            FMA2(a0[q], xa, w); FMA2(a1[q], xb, w);
        }
    }
    #pragma unroll
    for (int k = 0; k < 16; k++) {
        const ulonglong2* wr = (const ulonglong2*)(sWh + k * 64 + blk * 16);
        u64 ha = sH0[k * CTA + tid];
        u64 hb = sH1[k * CTA + tid];
        #pragma unroll
        for (int q = 0; q < 4; q++) {
            ulonglong2 w = wr[q];
            FMA2(a0[2*q+0], ha, w.x); FMA2(a1[2*q+0], hb, w.x);
            FMA2(a0[2*q+1], ha, w.y); FMA2(a1[2*q+1], hb, w.y);
        }
    }
}

__global__ __launch_bounds__(CTA, 5) void knet_kernel(
    const float* __restrict__ dyn_in,
    const float* __restrict__ lat_in_g,
    const float* __restrict__ lat_out_g,
    const float* __restrict__ h_g,
    const float* __restrict__ c_g,
    const float* __restrict__ Wh_g,
    float* __restrict__ out_dyn,
    float* __restrict__ out_lat,
    float* __restrict__ out_h,
    float* __restrict__ out_c)
{
    __shared__ __align__(16) float sWh[16 * 64];
    __shared__ u64 sH0[16 * CTA];   // h of cell0, pre-duplicated f32x2, [k][tid]
    __shared__ u64 sH1[16 * CTA];   // h of cell1

    for (int i = threadIdx.x; i < 16 * 64; i += CTA) sWh[i] = Wh_g[i];
    __syncthreads();

    int ltid = threadIdx.x;
    int tid = blockIdx.x * CTA + ltid;   // 0 .. 16*NP-1
    int p   = tid & (NP - 1);
    int b0  = tid >> 16;       // 0..15
    int b1  = b0 + 16;

    int r  = p >> 8;
    int cc = p & (NCOLS - 1);

    size_t cell0 = (size_t)b0 * NP + p;
    size_t cell1 = (size_t)b1 * NP + p;

    // ---------------- gather x = [dyn, lat_in(updated)] ----------------
    float x0[9], x1[9];
    x0[0] = dyn_in[cell0];
    x1[0] = dyn_in[cell1];
    {
        const float* lo0 = lat_out_g + ((size_t)b0 * NP) * 8;  // batch base
        const float* lo1 = lat_out_g + ((size_t)b1 * NP) * 8;
        const int drs[8] = {-1,-1,-1, 0, 0, 1, 1, 1};
        const int dcs[8] = {-1, 0, 1,-1, 1,-1, 0, 1};

        bool interior = (r > 0) & (r < 255) & (cc > 0) & (cc < 255);
        if (__all_sync(0xffffffffu, interior)) {
            #pragma unroll
            for (int d = 0; d < 8; d++) {
                int nb = (r + drs[d]) * NCOLS + (cc + dcs[d]);
                x0[1 + d] = lo0[(size_t)nb * 8 + d];
                x1[1 + d] = lo1[(size_t)nb * 8 + d];
            }
        } else {
            const float* li0 = lat_in_g + cell0 * 8;
            const float* li1 = lat_in_g + cell1 * 8;
            #pragma unroll
            for (int d = 0; d < 8; d++) {
                int nr = r + drs[d], nc = cc + dcs[d];
                bool valid = ((unsigned)nr < 256u) && ((unsigned)nc < 256u);
                int nb = nr * NCOLS + nc;
                float v0, v1;
                if (valid) {
                    v0 = lo0[(size_t)nb * 8 + d];
                    v1 = lo1[(size_t)nb * 8 + d];
                } else {
                    v0 = li0[d];
                    v1 = li1[d];
                }
                x0[1 + d] = v0;
                x1[1 + d] = v1;
            }
        }
    }

    // ---------------- stage h into per-thread SMEM columns (no sync needed:
    // each thread writes and reads only column ltid) ----------------
    {
        const float4* hp0 = (const float4*)(h_g + cell0 * 16);
        const float4* hp1 = (const float4*)(h_g + cell1 * 16);
        #pragma unroll
        for (int q = 0; q < 4; q++) {
            float4 v0 = hp0[q], v1 = hp1[q];
            sH0[(4*q+0) * CTA + ltid] = pack2(v0.x, v0.x);
            sH0[(4*q+1) * CTA + ltid] = pack2(v0.y, v0.y);
            sH0[(4*q+2) * CTA + ltid] = pack2(v0.z, v0.z);
            sH0[(4*q+3) * CTA + ltid] = pack2(v0.w, v0.w);
            sH1[(4*q+0) * CTA + ltid] = pack2(v1.x, v1.x);
            sH1[(4*q+1) * CTA + ltid] = pack2(v1.y, v1.y);
            sH1[(4*q+2) * CTA + ltid] = pack2(v1.z, v1.z);
            sH1[(4*q+3) * CTA + ltid] = pack2(v1.w, v1.w);
        }
    }

    u64 a0[8], a1[8];
    float keep0[16], keep1[16];   // g, then i*g, then c_new, then h_new

    // ---- block 2: g = tanh(...) ----
    gate_block2(sWh, sH0, sH1, ltid, 2, x0, x1, a0, a1);
    #pragma unroll
    for (int j = 0; j < 8; j++) {
        float f0, f1;
        unpack2(a0[j], f0, f1); keep0[2*j] = tanh_f(f0); keep0[2*j+1] = tanh_f(f1);
        unpack2(a1[j], f0, f1); keep1[2*j] = tanh_f(f0); keep1[2*j+1] = tanh_f(f1);
    }

    // ---- block 0: i = sigmoid(...); keep = i*g ----
    gate_block2(sWh, sH0, sH1, ltid, 0, x0, x1, a0, a1);
    #pragma unroll
    for (int j = 0; j < 8; j++) {
        float f0, f1;
        unpack2(a0[j], f0, f1); keep0[2*j] *= sig_f(f0); keep0[2*j+1] *= sig_f(f1);
        unpack2(a1[j], f0, f1); keep1[2*j] *= sig_f(f0); keep1[2*j+1] *= sig_f(f1);
    }

    // ---- block 1: f = sigmoid(...); keep = c_new = f*c + i*g ----
    // issue c loads BEFORE the FMA burst so their latency hides under it
    float4 cv0[4], cv1[4];
    {
        const float4* cp0 = (const float4*)(c_g + cell0 * 16);
        const float4* cp1 = (const float4*)(c_g + cell1 * 16);
        #pragma unroll
        for (int q = 0; q < 4; q++) { cv0[q] = cp0[q]; cv1[q] = cp1[q]; }
    }
    gate_block2(sWh, sH0, sH1, ltid, 1, x0, x1, a0, a1);
    {
        const float* cc0 = (const float*)cv0;
        const float* cc1 = (const float*)cv1;
        #pragma unroll
        for (int j = 0; j < 8; j++) {
            float f0, f1;
            unpack2(a0[j], f0, f1);
            keep0[2*j+0] = fmaf(sig_f(f0), cc0[2*j+0], keep0[2*j+0]);
            keep0[2*j+1] = fmaf(sig_f(f1), cc0[2*j+1], keep0[2*j+1]);
            unpack2(a1[j], f0, f1);
            keep1[2*j+0] = fmaf(sig_f(f0), cc1[2*j+0], keep1[2*j+0]);
            keep1[2*j+1] = fmaf(sig_f(f1), cc1[2*j+1], keep1[2*j+1]);
        }
    }

    // write c_new
    {
        float4* cp0 = (float4*)(out_c + cell0 * 16);
        float4* cp1 = (float4*)(out_c + cell1 * 16);
        #pragma unroll
        for (int q = 0; q < 4; q++) {
            cp0[q] = make_float4(keep0[4*q+0], keep0[4*q+1], keep0[4*q+2], keep0[4*q+3]);
            cp1[q] = make_float4(keep1[4*q+0], keep1[4*q+1], keep1[4*q+2], keep1[4*q+3]);
        }
    }

    // ---- block 3: o = sigmoid(...); keep = h_new = o * tanh(c_new) ----
    gate_block2(sWh, sH0, sH1, ltid, 3, x0, x1, a0, a1);
    #pragma unroll
    for (int j = 0; j < 8; j++) {
        float f0, f1;
        unpack2(a0[j], f0, f1);
        keep0[2*j]   = sig_f(f0) * tanh_f(keep0[2*j]);
        keep0[2*j+1] = sig_f(f1) * tanh_f(keep0[2*j+1]);
        unpack2(a1[j], f0, f1);
        keep1[2*j]   = sig_f(f0) * tanh_f(keep1[2*j]);
        keep1[2*j+1] = sig_f(f1) * tanh_f(keep1[2*j+1]);
    }

    // write h_new
    {
        float4* hp0 = (float4*)(out_h + cell0 * 16);
        float4* hp1 = (float4*)(out_h + cell1 * 16);
        #pragma unroll
        for (int q = 0; q < 4; q++) {
            hp0[q] = make_float4(keep0[4*q+0], keep0[4*q+1], keep0[4*q+2], keep0[4*q+3]);
            hp1[q] = make_float4(keep1[4*q+0], keep1[4*q+1], keep1[4*q+2], keep1[4*q+3]);
        }
    }

    // ---------------- output projection: out = tanh(h_new @ Wo + bo) ----------------
    float o0[9], o1[9];
    #pragma unroll
    for (int j = 0; j < 9; j++) {
        float a0s = cBo[j], a1s = cBo[j];
        #pragma unroll
        for (int k = 0; k < 16; k++) {
            float w = cWo[k * 9 + j];
            a0s = fmaf(keep0[k], w, a0s);
            a1s = fmaf(keep1[k], w, a1s);
        }
        o0[j] = tanh_f(a0s);
        o1[j] = tanh_f(a1s);
    }

    out_dyn[cell0] = o0[0];
    out_dyn[cell1] = o1[0];
    {
        float4* lp0 = (float4*)(out_lat + cell0 * 8);
        float4* lp1 = (float4*)(out_lat + cell1 * 8);
        lp0[0] = make_float4(o0[1], o0[2], o0[3], o0[4]);
        lp0[1] = make_float4(o0[5], o0[6], o0[7], o0[8]);
        lp1[0] = make_float4(o1[1], o1[2], o1[3], o1[4]);
        lp1[1] = make_float4(o1[5], o1[6], o1[7], o1[8]);
    }
}

extern "C" void kernel_launch(void* const* d_in, const int* in_sizes, int n_in,
                              void* d_out, int out_size) {
    const float* dyn_in   = (const float*)d_in[0];
    const float* lat_in   = (const float*)d_in[1];
    const float* lat_out  = (const float*)d_in[2];
    const float* h        = (const float*)d_in[3];
    const float* c        = (const float*)d_in[4];
    const float* Wx       = (const float*)d_in[5];
    const float* Wh       = (const float*)d_in[6];
    const float* bvec     = (const float*)d_in[7];
    const float* Wo       = (const float*)d_in[8];
    const float* bo       = (const float*)d_in[9];
    // d_in[10..12] = pos0 / coming_from / going_to : adjacency recomputed analytically.

    // Stage small weights into constant memory (D2D async, graph-capturable).
    cudaMemcpyToSymbolAsync(cWx, Wx,   9 * 64 * sizeof(float), 0, cudaMemcpyDeviceToDevice);
    cudaMemcpyToSymbolAsync(cB,  bvec,     64 * sizeof(float), 0, cudaMemcpyDeviceToDevice);
    cudaMemcpyToSymbolAsync(cWo, Wo,  16 * 9 * sizeof(float), 0, cudaMemcpyDeviceToDevice);
    cudaMemcpyToSymbolAsync(cBo, bo,        9 * sizeof(float), 0, cudaMemcpyDeviceToDevice);

    float* out = (float*)d_out;
    float* out_dyn = out;                                   // [B, P, 1]
    float* out_lat = out_dyn + (size_t)NBATCH * NP;         // [B, P, 8]
    float* out_h   = out_lat + (size_t)NBATCH * NP * 8;     // [B, P, 16]
    float* out_c   = out_h   + (size_t)NBATCH * NP * 16;    // [B, P, 16]

    int total_threads = (NBATCH / 2) * NP;   // 2 cells (batch halves) per thread
    int blocks = total_threads / CTA;
    knet_kernel<<<blocks, CTA>>>(dyn_in, lat_in, lat_out, h, c, Wh,
                                 out_dyn, out_lat, out_h, out_c);
}